// round 3
// baseline (speedup 1.0000x reference)
#include <cuda_runtime.h>
#include <cuda_bf16.h>

// DNN_84026740179139: embedding-bag mean (50/row) + 3x [64x64 Linear + ReLU], fused.
// R3: occupancy fix. 32 rows/block, 512 blocks, 256 threads -> 4096 warps (2x R2).
//   Gather: warp owns 4 rows (half-warp float4), NNZ unrolled x5 -> 10 LDGs in flight.
//   GEMM: 2 rows x 4 dims per thread (16x16 slots), sXt stride 34 (aligned float2,
//   conflict-free reads), per-layer W staged into 16KB shared.

#define BATCH   16384
#define DIMS    64
#define NNZ     50
#define RPB     32                  // rows per block
#define THREADS 256
#define GRID    (BATCH / RPB)       // 512
#define XTS     34                  // sXt row stride in floats (8B-aligned float2, clean banks)

__global__ __launch_bounds__(THREADS) void dnn_fused3_kernel(
    const float* __restrict__ emb,
    const int*   __restrict__ fidx,
    const float* __restrict__ W0, const float* __restrict__ b0,
    const float* __restrict__ W1, const float* __restrict__ b1,
    const float* __restrict__ b2, const float* __restrict__ W2,
    float* __restrict__ out)
{
    __shared__ float sW[DIMS * DIMS];      // 16 KB, staged per layer
    __shared__ float sXt[DIMS * XTS];      // 8.5 KB, x transposed: sXt[k*XTS + r]

    const int tid  = threadIdx.x;
    const int warp = tid >> 5;
    const int lane = tid & 31;

    // ---- Stage W0 (overlaps with gather LDGs) ----
    {
        const float4* src = (const float4*)W0;
        float4*       dst = (float4*)sW;
        #pragma unroll
        for (int s = 0; s < 4; s++)
            dst[tid + s * THREADS] = src[tid + s * THREADS];
    }

    // ---- Gather + mean. Warp owns 4 rows. half-warp per row: lane = 16*half + c,
    //      c covers dims 4c..4c+3. j=0..1 row pairs -> 2 LDG.128 per (i,j) step. ----
    const int half = lane >> 4;
    const int c    = lane & 15;
    const int rowsBase = blockIdx.x * RPB + warp * 4;   // global batch row

    const float4* emb4 = (const float4*)emb;
    float4 acc[2];
    acc[0] = make_float4(0.f, 0.f, 0.f, 0.f);
    acc[1] = make_float4(0.f, 0.f, 0.f, 0.f);

    // NNZ = 50 = 10 * 5 : unroll 5 -> 10 independent gathers in flight per thread
    #pragma unroll 1
    for (int i0 = 0; i0 < NNZ; i0 += 5) {
        #pragma unroll
        for (int u = 0; u < 5; u++) {
            #pragma unroll
            for (int j = 0; j < 2; j++) {
                const int row = rowsBase + 2 * j + half;
                const int id  = __ldg(fidx + row * NNZ + i0 + u);
                const float4 v = __ldg(&emb4[(size_t)id * (DIMS / 4) + c]);
                acc[j].x += v.x; acc[j].y += v.y; acc[j].z += v.z; acc[j].w += v.w;
            }
        }
    }
    const float inv = 1.0f / (float)NNZ;
    #pragma unroll
    for (int j = 0; j < 2; j++) {
        const int r = warp * 4 + 2 * j + half;          // row within block (0..31)
        sXt[(4 * c + 0) * XTS + r] = acc[j].x * inv;
        sXt[(4 * c + 1) * XTS + r] = acc[j].y * inv;
        sXt[(4 * c + 2) * XTS + r] = acc[j].z * inv;
        sXt[(4 * c + 3) * XTS + r] = acc[j].w * inv;
    }
    __syncthreads();

    // ---- MLP: 3 layers. Thread tile: 2 rows x 4 dims.
    //      tr = tid&15 -> rows 2*tr..+1 ; td = tid>>4 -> dims 4*td..+3 ----
    const int tr = tid & 15;
    const int td = tid >> 4;
    const int r0 = 2 * tr;
    const int d0 = 4 * td;

    const float* Wn[3] = {W0, W1, W2};
    const float* bn[3] = {b0, b1, b2};

    float y[2][4];

    #pragma unroll
    for (int l = 0; l < 3; l++) {
        const float4 bias = __ldg((const float4*)(bn[l]) + td);
        #pragma unroll
        for (int r = 0; r < 2; r++) {
            y[r][0] = bias.x; y[r][1] = bias.y; y[r][2] = bias.z; y[r][3] = bias.w;
        }

        #pragma unroll 16
        for (int k = 0; k < DIMS; k++) {
            const float2 xv = *(const float2*)(sXt + k * XTS  + r0);  // conflict-free
            const float4 wv = *(const float4*)(sW  + k * DIMS + d0);  // 2-addr broadcast
            y[0][0] = fmaf(xv.x, wv.x, y[0][0]);
            y[0][1] = fmaf(xv.x, wv.y, y[0][1]);
            y[0][2] = fmaf(xv.x, wv.z, y[0][2]);
            y[0][3] = fmaf(xv.x, wv.w, y[0][3]);
            y[1][0] = fmaf(xv.y, wv.x, y[1][0]);
            y[1][1] = fmaf(xv.y, wv.y, y[1][1]);
            y[1][2] = fmaf(xv.y, wv.z, y[1][2]);
            y[1][3] = fmaf(xv.y, wv.w, y[1][3]);
        }

        #pragma unroll
        for (int r = 0; r < 2; r++)
            #pragma unroll
            for (int d = 0; d < 4; d++)
                y[r][d] = fmaxf(y[r][d], 0.f);

        if (l < 2) {
            __syncthreads();   // all reads of sXt(l)/sW(l) complete
            // stage next layer's W
            {
                const float4* src = (const float4*)Wn[l + 1];
                float4*       dst = (float4*)sW;
                #pragma unroll
                for (int s = 0; s < 4; s++)
                    dst[tid + s * THREADS] = src[tid + s * THREADS];
            }
            // write y back transposed: Xt_next[d][r] = y[r][d]
            #pragma unroll
            for (int d = 0; d < 4; d++) {
                sXt[(d0 + d) * XTS + r0 + 0] = y[0][d];
                sXt[(d0 + d) * XTS + r0 + 1] = y[1][d];
            }
            __syncthreads();
        }
    }

    // ---- Store output [B, 64] ----
    #pragma unroll
    for (int r = 0; r < 2; r++) {
        float4 o = make_float4(y[r][0], y[r][1], y[r][2], y[r][3]);
        *(float4*)(out + (size_t)(blockIdx.x * RPB + r0 + r) * DIMS + d0) = o;
    }
}

extern "C" void kernel_launch(void* const* d_in, const int* in_sizes, int n_in,
                              void* d_out, int out_size)
{
    // Resolve inputs by element count:
    //   emb_table 6400000 f32; feature_indices 819200 i32 (first occurrence);
    //   W* 4096 f32 in order; b* 64 f32 in order.
    const float* emb  = nullptr;
    const int*   fidx = nullptr;
    const float* W[3] = {nullptr, nullptr, nullptr};
    const float* b[3] = {nullptr, nullptr, nullptr};
    int wi = 0, bi = 0;

    for (int i = 0; i < n_in; i++) {
        const int sz = in_sizes[i];
        if (sz == 100000 * 64) {
            emb = (const float*)d_in[i];
        } else if (sz == BATCH * NNZ) {
            if (!fidx) fidx = (const int*)d_in[i];
        } else if (sz == DIMS * DIMS) {
            if (wi < 3) W[wi++] = (const float*)d_in[i];
        } else if (sz == DIMS) {
            if (bi < 3) b[bi++] = (const float*)d_in[i];
        }
    }

    float* out = (float*)d_out;
    dnn_fused3_kernel<<<GRID, THREADS>>>(
        emb, fidx, W[0], b[0], W[1], b[1], b[2], W[2], out);
}

// round 4
// speedup vs baseline: 1.1120x; 1.1120x over previous
#include <cuda_runtime.h>
#include <cuda_bf16.h>

// DNN_84026740179139: embedding-bag mean (50/row) + 3x [64x64 Linear + ReLU], fused.
// R4: best-of-R2/R3 + idx staged in shared.
//   32 rows/block, 128 threads, grid 512 (~7 blocks/SM resident).
//   Block preloads its 1600 feature indices into shared (coalesced int4) ->
//   gather loop's idx read is a 29-cyc broadcast LDS, not a ~260-cyc LDG.
//   Gather: warp owns 8 rows, half-warp float4 lanes, 8 LDG.128 in flight.
//   GEMM: 4 rows x 4 dims per thread (16 FFMA per 2 LDS), per-layer W in shared.

#define BATCH   16384
#define DIMS    64
#define NNZ     50
#define RPB     32                  // rows per block
#define THREADS 128
#define GRID    (BATCH / RPB)       // 512
#define XTS     36                  // sXt row stride (floats, 16B-aligned)

__global__ __launch_bounds__(THREADS) void dnn_fused4_kernel(
    const float* __restrict__ emb,
    const int*   __restrict__ fidx,
    const float* __restrict__ W0, const float* __restrict__ b0,
    const float* __restrict__ W1, const float* __restrict__ b1,
    const float* __restrict__ b2, const float* __restrict__ W2,
    float* __restrict__ out)
{
    __shared__ int   sIdx[RPB * NNZ];      // 6.4 KB : this block's feature indices
    __shared__ float sW[DIMS * DIMS];      // 16 KB  : current layer weights
    __shared__ float sXt[DIMS * XTS];      // 9.2 KB : x transposed, sXt[k*XTS + r]

    const int tid  = threadIdx.x;
    const int warp = tid >> 5;
    const int lane = tid & 31;

    // ---- Stage this block's indices (contiguous 1600 ints) + W0, coalesced ----
    {
        const int4* src = (const int4*)(fidx + blockIdx.x * RPB * NNZ);
        int4*       dst = (int4*)sIdx;
        #pragma unroll
        for (int i = tid; i < (RPB * NNZ) / 4; i += THREADS)
            dst[i] = src[i];
        const float4* wsrc = (const float4*)W0;
        float4*       wdst = (float4*)sW;
        #pragma unroll
        for (int s = 0; s < 8; s++)
            wdst[tid + s * THREADS] = wsrc[tid + s * THREADS];
    }
    __syncthreads();

    // ---- Gather + mean. Warp owns 8 rows; half-warp per row (float4 lanes).
    //      lane = 16*half + c ; c covers dims 4c..4c+3. ----
    const int half = lane >> 4;
    const int c    = lane & 15;
    const int lrowBase = warp * 8;                       // row within block

    const float4* emb4 = (const float4*)emb;
    float4 acc[4];
    #pragma unroll
    for (int j = 0; j < 4; j++) acc[j] = make_float4(0.f, 0.f, 0.f, 0.f);

    // 8 independent gather LDG.128 in flight per thread (2 i-steps x 4 rows)
    #pragma unroll 1
    for (int i0 = 0; i0 < NNZ; i0 += 2) {
        #pragma unroll
        for (int u = 0; u < 2; u++) {
            #pragma unroll
            for (int j = 0; j < 4; j++) {
                const int lrow = lrowBase + 2 * j + half;
                const int id   = sIdx[lrow * NNZ + i0 + u];     // broadcast LDS
                const float4 v = __ldg(&emb4[(size_t)id * (DIMS / 4) + c]);
                acc[j].x += v.x; acc[j].y += v.y; acc[j].z += v.z; acc[j].w += v.w;
            }
        }
    }
    const float inv = 1.0f / (float)NNZ;
    #pragma unroll
    for (int j = 0; j < 4; j++) {
        const int r = lrowBase + 2 * j + half;
        sXt[(4 * c + 0) * XTS + r] = acc[j].x * inv;
        sXt[(4 * c + 1) * XTS + r] = acc[j].y * inv;
        sXt[(4 * c + 2) * XTS + r] = acc[j].z * inv;
        sXt[(4 * c + 3) * XTS + r] = acc[j].w * inv;
    }
    __syncthreads();

    // ---- MLP: 3 layers, shared-mem GEMM, 4 rows x 4 dims per thread.
    //      tr = tid&7 -> rows 4*tr..+3 ; td = tid>>3 -> dims 4*td..+3 ----
    const int r0 = 4 * (tid & 7);
    const int d0 = 4 * (tid >> 3);

    const float* Wn[3] = {W0, W1, W2};
    const float* bn[3] = {b0, b1, b2};

    float y[4][4];

    #pragma unroll
    for (int l = 0; l < 3; l++) {
        const float4 bias = __ldg((const float4*)(bn[l]) + (d0 >> 2));
        #pragma unroll
        for (int r = 0; r < 4; r++) {
            y[r][0] = bias.x; y[r][1] = bias.y; y[r][2] = bias.z; y[r][3] = bias.w;
        }

        #pragma unroll 16
        for (int k = 0; k < DIMS; k++) {
            const float4 xv = *(const float4*)(sXt + k * XTS  + r0);  // 8 distinct/warp
            const float4 wv = *(const float4*)(sW  + k * DIMS + d0);  // 4 distinct/warp
            const float xr[4] = {xv.x, xv.y, xv.z, xv.w};
            #pragma unroll
            for (int r = 0; r < 4; r++) {
                y[r][0] = fmaf(xr[r], wv.x, y[r][0]);
                y[r][1] = fmaf(xr[r], wv.y, y[r][1]);
                y[r][2] = fmaf(xr[r], wv.z, y[r][2]);
                y[r][3] = fmaf(xr[r], wv.w, y[r][3]);
            }
        }

        #pragma unroll
        for (int r = 0; r < 4; r++)
            #pragma unroll
            for (int d = 0; d < 4; d++)
                y[r][d] = fmaxf(y[r][d], 0.f);

        if (l < 2) {
            __syncthreads();   // all reads of sXt(l)/sW(l) complete
            {
                const float4* src = (const float4*)Wn[l + 1];
                float4*       dst = (float4*)sW;
                #pragma unroll
                for (int s = 0; s < 8; s++)
                    dst[tid + s * THREADS] = src[tid + s * THREADS];
            }
            // write y back transposed: Xt_next[d][r0..r0+3] (aligned float4)
            #pragma unroll
            for (int d = 0; d < 4; d++) {
                float4 col = make_float4(y[0][d], y[1][d], y[2][d], y[3][d]);
                *(float4*)(sXt + (d0 + d) * XTS + r0) = col;
            }
            __syncthreads();
        }
    }

    // ---- Store output [B, 64] ----
    #pragma unroll
    for (int r = 0; r < 4; r++) {
        float4 o = make_float4(y[r][0], y[r][1], y[r][2], y[r][3]);
        *(float4*)(out + (size_t)(blockIdx.x * RPB + r0 + r) * DIMS + d0) = o;
    }
}

extern "C" void kernel_launch(void* const* d_in, const int* in_sizes, int n_in,
                              void* d_out, int out_size)
{
    // Resolve inputs by element count:
    //   emb_table 6400000 f32; feature_indices 819200 i32 (first occurrence);
    //   W* 4096 f32 in order; b* 64 f32 in order.
    const float* emb  = nullptr;
    const int*   fidx = nullptr;
    const float* W[3] = {nullptr, nullptr, nullptr};
    const float* b[3] = {nullptr, nullptr, nullptr};
    int wi = 0, bi = 0;

    for (int i = 0; i < n_in; i++) {
        const int sz = in_sizes[i];
        if (sz == 100000 * 64) {
            emb = (const float*)d_in[i];
        } else if (sz == BATCH * NNZ) {
            if (!fidx) fidx = (const int*)d_in[i];
        } else if (sz == DIMS * DIMS) {
            if (wi < 3) W[wi++] = (const float*)d_in[i];
        } else if (sz == DIMS) {
            if (bi < 3) b[bi++] = (const float*)d_in[i];
        }
    }

    float* out = (float*)d_out;
    dnn_fused4_kernel<<<GRID, THREADS>>>(
        emb, fidx, W[0], b[0], W[1], b[1], b[2], W[2], out);
}